// round 5
// baseline (speedup 1.0000x reference)
#include <cuda_runtime.h>
#include <cstdint>

#define BB 512
#define TT 8192
#define KW 5
#define NTH 128
#define WPB 4
#define CL 128                 // steps per lane
#define CLF4 32                // float4s per lane chunk
#define WARP_F4 1024           // float4s per warp region (4096 steps)
#define HALO_F4 48             // 192-step speculative warmup halo
#define SLICE_F4 (WARP_F4 + HALO_F4)   // 1072

// XOR swizzle on float4 index (lane stride is 32 f4 -> use bit 5+).
// Conflict-free for: stride-32-lane reads (warm/real), contiguous-32 writes
// (cp.async, writeback) -- every 8-lane phase hits 8 distinct 16B bank-quads.
#define QS(u) ((u) ^ ((((unsigned)(u)) >> 5) & 7))

#define SMEM_DYN (WPB * 3 * SLICE_F4 * 16)   // 205,824 bytes

__device__ __forceinline__ uint32_t smem_u32(const void* p) {
    uint32_t a;
    asm("{ .reg .u64 t; cvta.to.shared.u64 t, %1; cvt.u32.u64 %0, t; }"
        : "=r"(a) : "l"(p));
    return a;
}

__device__ __forceinline__ float fset_ge1(float c) {
    float r;
    asm("set.ge.f32.f32 %0, %1, 0f3F800000;" : "=f"(r) : "f"(c));
    return r;
}

__device__ __forceinline__ void insert5(float kk[KW], float x) {
    kk[4] = fmaxf(kk[4], x);
#pragma unroll
    for (int j = 4; j >= 1; j--) {
        float hi = fmaxf(kk[j - 1], kk[j]);
        float lo = fminf(kk[j - 1], kk[j]);
        kk[j - 1] = hi; kk[j] = lo;
    }
}

// Warm step: state only. Exact XLA semantics (separate mul/add; Sterbenz-exact c-1).
#define WSTEP(xa, xp, xb) do {                        \
    float c0 = __fadd_rn(__fmul_rn(d0, v0), (xa));    \
    float c1 = __fadd_rn(__fmul_rn(d1, v1), (xp));    \
    float c2 = __fadd_rn(__fmul_rn(d2, v2), (xb));    \
    v0 = __fadd_rn(c0, -fset_ge1(c0));                \
    v1 = __fadd_rn(c1, -fset_ge1(c1));                \
    v2 = __fadd_rn(c2, -fset_ge1(c2));                \
} while (0)

__device__ __forceinline__ float rstep(float& v0, float& v1, float& v2,
                                       float d0, float d1, float d2,
                                       float w0, float w1, float w2,
                                       float xa, float xp, float xb) {
    float c0 = __fadd_rn(__fmul_rn(d0, v0), xa);
    float c1 = __fadd_rn(__fmul_rn(d1, v1), xp);
    float c2 = __fadd_rn(__fmul_rn(d2, v2), xb);
    float s0 = fset_ge1(c0), s1 = fset_ge1(c1), s2 = fset_ge1(c2);
    v0 = __fadd_rn(c0, -s0);
    v1 = __fadd_rn(c1, -s1);
    v2 = __fadd_rn(c2, -s2);
    return __fmaf_rn(s2, w2, __fmaf_rn(s1, w1, __fmul_rn(s0, w0)));
}

__global__ void __launch_bounds__(NTH, 1) fused_kernel(
    const float* __restrict__ amp, const float* __restrict__ pitch,
    const float* __restrict__ boundary, const float* __restrict__ decay,
    const float* __restrict__ weights, float* __restrict__ out)
{
    extern __shared__ float4 sm4[];
    __shared__ float mk[NTH * KW];
    __shared__ float s_den[2];

    int tid = threadIdx.x;
    int w   = tid >> 5;
    int l   = tid & 31;
    int wr  = w & 1;                        // warp-in-row (0: first half, 1: second)
    int row = 2 * blockIdx.x + (w >> 1);    // warps 0,1 -> row A; 2,3 -> row B
    long rowf4 = (long)row * (TT / 4);

    float d0 = __ldg(decay),   d1 = __ldg(decay + 1),   d2 = __ldg(decay + 2);
    float w0 = __ldg(weights), w1 = __ldg(weights + 1), w2 = __ldg(weights + 2);

    float4* SA = sm4 + (w * 3 + 0) * SLICE_F4;
    float4* SP = sm4 + (w * 3 + 1) * SLICE_F4;
    float4* SB = sm4 + (w * 3 + 2) * SLICE_F4;
    uint32_t sa_u = smem_u32(SA), sp_u = smem_u32(SP), sb_u = smem_u32(SB);

    const float4* gA = (const float4*)amp      + rowf4;
    const float4* gP = (const float4*)pitch    + rowf4;
    const float4* gB = (const float4*)boundary + rowf4;

    // ---- issue all slice loads async (warp-autonomous) ----
    int g0 = wr * WARP_F4 - HALO_F4;
    for (int j = l; j < SLICE_F4; j += 32) {
        int src = g0 + j;
        uint32_t off = (uint32_t)QS(j) * 16u;
        if (src >= 0) {
            asm volatile("cp.async.ca.shared.global [%0], [%1], 16;"
                         :: "r"(sa_u + off), "l"(gA + src));
            asm volatile("cp.async.ca.shared.global [%0], [%1], 16;"
                         :: "r"(sp_u + off), "l"(gP + src));
            asm volatile("cp.async.ca.shared.global [%0], [%1], 16;"
                         :: "r"(sb_u + off), "l"(gB + src));
        } else {
            // row-start halo: zeros are EXACT (v stays 0 through zero prefix)
            float4 z = make_float4(0.f, 0.f, 0.f, 0.f);
            SA[QS(j)] = z; SP[QS(j)] = z; SB[QS(j)] = z;
        }
    }
    asm volatile("cp.async.wait_all;" ::: "memory");
    __syncwarp();

    // ---- warmup: 192 steps (48 f4) before own chunk ----
    float v0 = 0.f, v1 = 0.f, v2 = 0.f;
    int ub = CLF4 * l;
#pragma unroll 4
    for (int j = 0; j < HALO_F4; j++) {
        int u = QS(ub + j);
        float4 xa = SA[u], xp = SP[u], xb = SB[u];
        WSTEP(xa.x, xp.x, xb.x);
        WSTEP(xa.y, xp.y, xb.y);
        WSTEP(xa.z, xp.z, xb.z);
        WSTEP(xa.w, xp.w, xb.w);
    }
    __syncwarp();   // all warm reads done before any stash overwrites

    // ---- real chunk: 128 steps; stash vals in place; inline top-5 ----
    float kk[KW];
#pragma unroll
    for (int j = 0; j < KW; j++) kk[j] = -3.0e38f;
    int trow0 = wr * (WARP_F4 * 4) + l * CL;    // within-row step index

#pragma unroll 4
    for (int j = 0; j < CLF4; j++) {
        int u = QS(ub + HALO_F4 + j);
        float4 xa = SA[u], xp = SP[u], xb = SB[u];
        float4 val;
        val.x = rstep(v0, v1, v2, d0, d1, d2, w0, w1, w2, xa.x, xp.x, xb.x);
        val.y = rstep(v0, v1, v2, d0, d1, d2, w0, w1, w2, xa.y, xp.y, xb.y);
        val.z = rstep(v0, v1, v2, d0, d1, d2, w0, w1, w2, xa.z, xp.z, xb.z);
        val.w = rstep(v0, v1, v2, d0, d1, d2, w0, w1, w2, xa.w, xp.w, xb.w);
        SA[u] = val;   // same-lane same-address overwrite: safe

        float base = -(float)(trow0 + 4 * j);
        float k0 = __fmaf_rn(val.x, 8192.f, base);
        float k1 = __fmaf_rn(val.y, 8192.f, base - 1.f);
        float k2 = __fmaf_rn(val.z, 8192.f, base - 2.f);
        float k3 = __fmaf_rn(val.w, 8192.f, base - 3.f);
        float m = fmaxf(fmaxf(k0, k1), fmaxf(k2, k3));
        if (m > kk[4]) { insert5(kk, k0); insert5(kk, k1); insert5(kk, k2); insert5(kk, k3); }
    }

    // ---- per-row tree merge: two independent 64-thread merges ----
#pragma unroll
    for (int j = 0; j < KW; j++) mk[tid * KW + j] = kk[j];
    __syncthreads();
    int lid   = tid & 63;
    int hbase = tid & 64;
    for (int s = 32; s >= 1; s >>= 1) {
        if (lid < s) {
#pragma unroll
            for (int j = 0; j < KW; j++) {
                float x = mk[(hbase + lid + s) * KW + j];
                if (x > kk[4]) insert5(kk, x);
            }
#pragma unroll
            for (int j = 0; j < KW; j++) mk[tid * KW + j] = kk[j];
        }
        __syncthreads();
    }

    // ---- half-leaders: decode winners, mu, topk_idx; broadcast denom ----
    if (lid == 0) {
        float vmax = ceilf(kk[0] * (1.0f / 8192.0f));   // exact: integer counts
        float den  = __fadd_rn(vmax, 1e-6f);
        float ssum = 0.f;
        float* oi = out + BB + (long)BB * TT + row * KW;
#pragma unroll
        for (int j = 0; j < KW; j++) {
            float vj = ceilf(kk[j] * (1.0f / 8192.0f));
            float ij = __fmaf_rn(vj, 8192.0f, -kk[j]);  // exact integer index
            oi[j] = ij;
            ssum = __fadd_rn(ssum, vj / den);
        }
        float avg = ssum * 0.2f;
        out[row] = 0.5f + 2.0f * tanhf(1.8f * avg);
        s_den[tid >> 6] = den;
    }
    __syncthreads();

    // ---- writeback: coalesced float4 stores of normalized sal ----
    float inv = 1.0f / s_den[w >> 1];
    float4* go = (float4*)(out + BB) + rowf4 + wr * WARP_F4;
#pragma unroll 4
    for (int i = 0; i < WARP_F4 / 32; i++) {
        int o = 32 * i + l;
        float4 v = SA[QS(HALO_F4 + o)];
        go[o] = make_float4(v.x * inv, v.y * inv, v.z * inv, v.w * inv);
    }
}

extern "C" void kernel_launch(void* const* d_in, const int* in_sizes, int n_in,
                              void* d_out, int out_size) {
    const float* amp      = (const float*)d_in[0];
    const float* pitch    = (const float*)d_in[1];
    const float* boundary = (const float*)d_in[2];
    const float* decay    = (const float*)d_in[3];
    const float* weights  = (const float*)d_in[4];
    float* out = (float*)d_out;

    cudaFuncSetAttribute(fused_kernel,
                         cudaFuncAttributeMaxDynamicSharedMemorySize, SMEM_DYN);
    // Output layout: [mu (512)] [sal (512*8192)] [topk_idx (512*5) as f32]
    fused_kernel<<<BB / 2, NTH, SMEM_DYN>>>(amp, pitch, boundary, decay, weights, out);
}